// round 17
// baseline (speedup 1.0000x reference)
#include <cuda_runtime.h>
#include <cuda_fp16.h>
#include <math.h>
#include <cstdint>

// Problem constants
#define Bn 2
#define Tn 2048
#define Cn 1024
#define Hn 16
#define Dn 64
#define Mrows (Bn * Tn)   // 4096

// Scratch (allocation-free). fp16 everywhere except final output.
__device__ __half g_q[(size_t)Mrows * Cn];
__device__ __half g_k[(size_t)Mrows * Cn];
__device__ __half g_v[(size_t)Mrows * Cn];
__device__ __half g_y[(size_t)Mrows * Cn];
__device__ __half g_xh[(size_t)Mrows * Cn];       // fp16 x
__device__ __half g_wh[4][(size_t)Cn * Cn];       // fp16 Wq,Wk,Wv,Wo

// ---------------------------------------------------------------------------
// Helpers
// ---------------------------------------------------------------------------
__device__ __forceinline__ uint32_t smem_u32(const void* p) {
    uint32_t a;
    asm("{ .reg .u64 t; cvta.to.shared.u64 t, %1; cvt.u32.u64 %0, t; }" : "=r"(a) : "l"(p));
    return a;
}
__device__ __forceinline__ void cp16(uint32_t dst, const void* src) {
    asm volatile("cp.async.cg.shared.global [%0], [%1], 16;" :: "r"(dst), "l"(src));
}
#define CP_COMMIT() asm volatile("cp.async.commit_group;" ::: "memory")
#define CP_WAIT1()  asm volatile("cp.async.wait_group 1;" ::: "memory")

__device__ __forceinline__ void ldsm_x4(uint32_t* r, uint32_t addr) {
    asm volatile("ldmatrix.sync.aligned.m8n8.x4.shared.b16 {%0,%1,%2,%3}, [%4];"
                 : "=r"(r[0]), "=r"(r[1]), "=r"(r[2]), "=r"(r[3]) : "r"(addr));
}
__device__ __forceinline__ void ldsm_x4_t(uint32_t* r, uint32_t addr) {
    asm volatile("ldmatrix.sync.aligned.m8n8.x4.trans.shared.b16 {%0,%1,%2,%3}, [%4];"
                 : "=r"(r[0]), "=r"(r[1]), "=r"(r[2]), "=r"(r[3]) : "r"(addr));
}

// D(16x8) += A(16x16) * B(16x8), fp16 inputs, fp32 accum
__device__ __forceinline__ void mma_f16(float* d, const uint32_t* a,
                                        uint32_t b0, uint32_t b1) {
    asm volatile(
        "mma.sync.aligned.m16n8k16.row.col.f32.f16.f16.f32 "
        "{%0,%1,%2,%3}, {%4,%5,%6,%7}, {%8,%9}, {%0,%1,%2,%3};"
        : "+f"(d[0]), "+f"(d[1]), "+f"(d[2]), "+f"(d[3])
        : "r"(a[0]), "r"(a[1]), "r"(a[2]), "r"(a[3]), "r"(b0), "r"(b1));
}
// pack two f32 -> one u32 holding half2 (single PTX cvt)
__device__ __forceinline__ uint32_t pack_h2(float x, float y) {
    uint32_t r;
    asm("cvt.rn.f16x2.f32 %0, %1, %2;" : "=r"(r) : "f"(y), "f"(x));
    return r;
}

// ---------------------------------------------------------------------------
// Prep: convert x and weights to fp16
// ---------------------------------------------------------------------------
__global__ void prep_h(const float* __restrict__ x,
                       const float* __restrict__ wq, const float* __restrict__ wk,
                       const float* __restrict__ wv, const float* __restrict__ wo)
{
    const int seg = blockIdx.y;
    const float* src;
    __half* dst;
    int n2;
    if (seg == 0) { src = x; dst = g_xh; n2 = Mrows * Cn / 2; }
    else {
        src = (seg == 1) ? wq : (seg == 2) ? wk : (seg == 3) ? wv : wo;
        dst = g_wh[seg - 1];
        n2 = Cn * Cn / 2;
    }
    const int i = blockIdx.x * blockDim.x + threadIdx.x;
    if (i < n2) {
        float2 v = ((const float2*)src)[i];
        ((__half2*)dst)[i] = __float22half2_rn(v);
    }
}

// ---------------------------------------------------------------------------
// GEMM: C[M,N] = A[M,K] @ W[N,K]^T (fp16 mma.m16n8k16 + ldmatrix, fp32 accum).
// CTA 64x64, 128 threads (4 warps, each a 16x64 stripe), BK=64, 3-stage cp.async.
// 4 CTAs/SM -> 4 independent barrier domains per SM.
// q output (z==0, rope) additionally scaled by 0.125.
// ---------------------------------------------------------------------------
#define GEMM_SMEM_BYTES 49152   // 2 matrices x 3 stages x 8192 B

template <bool OH>
__global__ __launch_bounds__(128, 4) void gemm_h(
    const __half* __restrict__ A,
    const __half* __restrict__ W0, const __half* __restrict__ W1, const __half* __restrict__ W2,
    void* __restrict__ C0v, void* __restrict__ C1v, void* __restrict__ C2v,
    int do_rope)
{
    extern __shared__ char smc[];
    const uint32_t smbA = smem_u32(smc);
    const uint32_t smbB = smbA + 3 * 8192;

    const int z = blockIdx.z;
    const __half* W = (z == 0) ? W0 : ((z == 1) ? W1 : W2);
    void*        Cv = (z == 0) ? C0v : ((z == 1) ? C1v : C2v);
    const bool rope = (do_rope != 0) && (z < 2);
    const float oscale = (do_rope != 0 && z == 0) ? 0.125f : 1.0f;

    const int tid = threadIdx.x;
    const int wid = tid >> 5, lane = tid & 31;
    const int lq = lane >> 2, lr4 = lane & 3;
    const int m0 = wid * 16;                      // warp stripe: 16 rows x 64 cols
    const int rowBase = blockIdx.y * 64;
    const int colBase = blockIdx.x * 64;

    // cp.async: 64 rows x 128B per matrix per stage; 2 threads/row, 4 chunks each
    const int cr = tid >> 1, hlf = tid & 1;
    const __half* Ag = A + (size_t)(rowBase + cr) * Cn + hlf * 32;
    const __half* Wg = W + (size_t)(colBase + cr) * Cn + hlf * 32;
    uint32_t dOf[4];
#pragma unroll
    for (int i = 0; i < 4; i++) {
        const int chunk = hlf * 4 + i;
        dOf[i] = (uint32_t)(cr * 128 + ((chunk ^ (cr & 7)) << 4));
    }

#define G_ISSUE(t, s) do {                                            \
        const __half* _ga = Ag + (t) * 64;                            \
        const __half* _gw = Wg + (t) * 64;                            \
        const uint32_t _ba = smbA + (s) * 8192;                       \
        const uint32_t _bb = smbB + (s) * 8192;                       \
        _Pragma("unroll")                                             \
        for (int _i = 0; _i < 4; _i++) {                              \
            cp16(_ba + dOf[_i], _ga + _i * 8);                        \
            cp16(_bb + dOf[_i], _gw + _i * 8);                        \
        }                                                             \
    } while (0)

    G_ISSUE(0, 0); CP_COMMIT();
    G_ISSUE(1, 1); CP_COMMIT();

    // ldmatrix address components
    const int lane15 = lane & 15;
    const int aBit = lane >> 4;
    const int bBit = (lane >> 3) & 1;
    const int arow = m0 + lane15;
    const uint32_t aOff = (uint32_t)(arow * 128);
    const int aSwz = arow & 7;
    uint32_t bOff[4]; int bSwz[4];
#pragma unroll
    for (int p = 0; p < 4; p++) {
        const int n = p * 16 + ((lane >> 4) << 3) + (lane & 7);
        bOff[p] = (uint32_t)(n * 128);
        bSwz[p] = n & 7;
    }

    float acc[8][4];
#pragma unroll
    for (int j = 0; j < 8; j++)
#pragma unroll
        for (int k = 0; k < 4; k++) acc[j][k] = 0.f;

#pragma unroll 1
    for (int t = 0; t < 16; t++) {
        CP_WAIT1();
        __syncthreads();
        if (t + 2 < 16) G_ISSUE(t + 2, (t + 2) % 3);
        CP_COMMIT();

        const uint32_t sAa = smbA + (t % 3) * 8192;
        const uint32_t sBa = smbB + (t % 3) * 8192;
#pragma unroll
        for (int ks = 0; ks < 4; ks++) {
            uint32_t a[4], bf[4][4];
            ldsm_x4(a, sAa + aOff + (uint32_t)(((ks * 2 + aBit) ^ aSwz) << 4));
#pragma unroll
            for (int p = 0; p < 4; p++)
                ldsm_x4(bf[p], sBa + bOff[p] +
                        (uint32_t)(((ks * 2 + bBit) ^ bSwz[p]) << 4));
#pragma unroll
            for (int nf = 0; nf < 8; nf++)
                mma_f16(acc[nf], a, bf[nf >> 1][(nf & 1) * 2], bf[nf >> 1][(nf & 1) * 2 + 1]);
        }
    }

    // Epilogue: rows r0 = rowBase+m0+lq and r0+8; cols colBase + nf*8 + 2*lr4
    const float KLOG = 13.287712379549449f / 32.0f;   // log2(10000)/32
    const int r0 = rowBase + m0 + lq;
    if (OH) {
        __half* Cm = (__half*)Cv;
        if (!rope) {
#pragma unroll
            for (int nf = 0; nf < 8; nf++) {
                const int c0 = colBase + nf * 8 + 2 * lr4;
                *(__half2*)&Cm[(size_t)r0 * Cn + c0] =
                    __float22half2_rn(make_float2(acc[nf][0], acc[nf][1]));
                *(__half2*)&Cm[(size_t)(r0 + 8) * Cn + c0] =
                    __float22half2_rn(make_float2(acc[nf][2], acc[nf][3]));
            }
        } else {
            const int t0 = r0 & (Tn - 1), t1 = (r0 + 8) & (Tn - 1);
#pragma unroll
            for (int nf = 0; nf < 4; nf++) {       // d in [0,32): partner frag nf+4
                const int dlo = nf * 8 + 2 * lr4;  // colBase is head-aligned (64)
                const int c0 = colBase + dlo;
#pragma unroll
                for (int e = 0; e < 2; e++) {
                    const float freq = exp2f(-(float)(dlo + e) * KLOG);
                    float s0, cth0, s1, cth1;
                    sincosf((float)t0 * freq, &s0, &cth0);
                    sincosf((float)t1 * freq, &s1, &cth1);
                    const float lo0 = acc[nf][e],     hi0 = acc[nf + 4][e];
                    const float lo1 = acc[nf][e + 2], hi1 = acc[nf + 4][e + 2];
                    Cm[(size_t)r0 * Cn + c0 + e] =
                        __float2half_rn((lo0 * cth0 - hi0 * s0) * oscale);
                    Cm[(size_t)r0 * Cn + c0 + e + 32] =
                        __float2half_rn((hi0 * cth0 + lo0 * s0) * oscale);
                    Cm[(size_t)(r0 + 8) * Cn + c0 + e] =
                        __float2half_rn((lo1 * cth1 - hi1 * s1) * oscale);
                    Cm[(size_t)(r0 + 8) * Cn + c0 + e + 32] =
                        __float2half_rn((hi1 * cth1 + lo1 * s1) * oscale);
                }
            }
        }
    } else {
        float* Cm = (float*)Cv;
#pragma unroll
        for (int nf = 0; nf < 8; nf++) {
            const int c0 = colBase + nf * 8 + 2 * lr4;
            *(float2*)&Cm[(size_t)r0 * Cn + c0] = make_float2(acc[nf][0], acc[nf][1]);
            *(float2*)&Cm[(size_t)(r0 + 8) * Cn + c0] = make_float2(acc[nf][2], acc[nf][3]);
        }
    }
#undef G_ISSUE
}

// ---------------------------------------------------------------------------
// Flash attention FA2-style, k-tile=128 (two 64-col sub-chunks per cp.async
// stage: half the barriers/waits). 8 warps x 16 rows, S/P in registers.
// Smem bytes: Q 16384 | K 3x16384 | V 3x16384 = 114688. 2 CTAs/SM.
// ---------------------------------------------------------------------------
#define QB 0
#define KB 16384
#define VB 65536
#define ATTN_SMEM_BYTES 114688

__global__ __launch_bounds__(256, 2) void attn_h(
    const __half* __restrict__ Qg, const __half* __restrict__ Kg,
    const __half* __restrict__ Vg, __half* __restrict__ Yg)
{
    extern __shared__ char smc[];
    const uint32_t smb = smem_u32(smc);

    const int qi = (int)(gridDim.x - 1 - blockIdx.x);   // long tiles first
    const int h = blockIdx.y, b = blockIdx.z;
    const int tid = threadIdx.x;
    const int wid = tid >> 5, lane = tid & 31;
    const int lq = lane >> 2, lr4 = lane & 3;
    const int m0 = wid * 16;

    // cp.async mappings: 128 rows x 128B per tile; 2 threads/row, 4 chunks each
    const int qr = tid >> 1, qci = tid & 1;
    const __half* Qp = Qg + (size_t)(b * Tn + qi * 128 + qr) * Cn + h * 64 + qci * 32;
    const __half* Kp = Kg + (size_t)(b * Tn + qr) * Cn + h * 64 + qci * 32;
    const __half* Vp = Vg + (size_t)(b * Tn + qr) * Cn + h * 64 + qci * 32;
    uint32_t rOf[4];
#pragma unroll
    for (int i = 0; i < 4; i++) {
        const int chunk = qci * 4 + i;
        rOf[i] = (uint32_t)(qr * 128 + ((chunk ^ (qr & 7)) << 4));
    }

#define KV_ISSUE(j, s) do {                                                     \
        const __half* _kp = Kp + (size_t)((j) * 128) * Cn;                      \
        const __half* _vp = Vp + (size_t)((j) * 128) * Cn;                      \
        const uint32_t _bk = smb + KB + (s) * 16384;                            \
        const uint32_t _bv = smb + VB + (s) * 16384;                            \
        _Pragma("unroll")                                                       \
        for (int _i = 0; _i < 4; _i++) {                                        \
            cp16(_bk + rOf[_i], _kp + _i * 8);                                  \
            cp16(_bv + rOf[_i], _vp + _i * 8);                                  \
        }                                                                       \
    } while (0)

    // Prologue: Q + KV(0) in group0; KV(1) group1
#pragma unroll
    for (int i = 0; i < 4; i++)
        cp16(smb + QB + rOf[i], Qp + i * 8);
    KV_ISSUE(0, 0); CP_COMMIT();
    KV_ISSUE(1, 1); CP_COMMIT();

    // ldmatrix address components
    const int lane15 = lane & 15;
    const int aBit = lane >> 4;
    const int bBit = (lane >> 3) & 1;
    const int qrow = m0 + lane15;
    const uint32_t qOff = (uint32_t)(qrow * 128);
    const int qSwz = qrow & 7;
    uint32_t kOff[4]; int kSwz[4];
#pragma unroll
    for (int p = 0; p < 4; p++) {
        const int n = p * 16 + ((lane >> 4) << 3) + (lane & 7);
        kOff[p] = (uint32_t)(n * 128);
        kSwz[p] = n & 7;
    }
    const int vkl = ((lane >> 3) & 1) * 8 + (lane & 7);   // V trans k-row within 16
    const int vch = lane >> 4;                            // V trans chunk parity

    // Register state
    float o[8][4];
#pragma unroll
    for (int j = 0; j < 8; j++)
#pragma unroll
        for (int k = 0; k < 4; k++) o[j][k] = 0.f;
    float mOld0 = -1e30f, mOld1 = -1e30f, l0 = 0.f, l1 = 0.f;

    const int jmax = qi + 1;
#pragma unroll 1
    for (int j = 0; j < jmax; j++) {
        CP_WAIT1();
        __syncthreads();
        if (j + 2 < jmax) KV_ISSUE(j + 2, (j + 2) % 3);
        CP_COMMIT();

        const uint32_t sQa = smb + QB;
        const uint32_t sKa = smb + KB + (j % 3) * 16384;
        const uint32_t sVa = smb + VB + (j % 3) * 16384;

#pragma unroll
        for (int sub = 0; sub < 2; sub++) {
            const uint32_t kbase = sKa + sub * 8192;
            const uint32_t vbase = sVa + sub * 8192;
            const int jj = 2 * j + sub;             // 64-col block index

            // ---- S = Q K^T : warp stripe 16 x 64, S in registers ----
            float s[8][4];
#pragma unroll
            for (int nf = 0; nf < 8; nf++)
#pragma unroll
                for (int k = 0; k < 4; k++) s[nf][k] = 0.f;
#pragma unroll
            for (int ks = 0; ks < 4; ks++) {
                uint32_t a[4], bf[4][4];
                ldsm_x4(a, sQa + qOff + (uint32_t)(((ks * 2 + aBit) ^ qSwz) << 4));
#pragma unroll
                for (int p = 0; p < 4; p++)
                    ldsm_x4(bf[p], kbase + kOff[p] +
                            (uint32_t)(((ks * 2 + bBit) ^ kSwz[p]) << 4));
#pragma unroll
                for (int nf = 0; nf < 8; nf++)
                    mma_f16(s[nf], a, bf[nf >> 1][(nf & 1) * 2],
                            bf[nf >> 1][(nf & 1) * 2 + 1]);
            }

            // ---- causal mask (diagonal blocks only) ----
            if (jj >= 2 * qi) {
                const int mg0 = qi * 128 + m0 + lq, mg1 = mg0 + 8;
                const int cb = jj * 64 + 2 * lr4;
#pragma unroll
                for (int nf = 0; nf < 8; nf++) {
                    const int cg0 = cb + nf * 8, cg1 = cg0 + 1;
                    if (cg0 > mg0) s[nf][0] = -1e30f;
                    if (cg1 > mg0) s[nf][1] = -1e30f;
                    if (cg0 > mg1) s[nf][2] = -1e30f;
                    if (cg1 > mg1) s[nf][3] = -1e30f;
                }
            }

            // ---- online softmax in registers (quad = one row) ----
            float mx0 = -1e30f, mx1 = -1e30f;
#pragma unroll
            for (int nf = 0; nf < 8; nf++) {
                mx0 = fmaxf(mx0, fmaxf(s[nf][0], s[nf][1]));
                mx1 = fmaxf(mx1, fmaxf(s[nf][2], s[nf][3]));
            }
            mx0 = fmaxf(mx0, __shfl_xor_sync(0xffffffffu, mx0, 1));
            mx0 = fmaxf(mx0, __shfl_xor_sync(0xffffffffu, mx0, 2));
            mx1 = fmaxf(mx1, __shfl_xor_sync(0xffffffffu, mx1, 1));
            mx1 = fmaxf(mx1, __shfl_xor_sync(0xffffffffu, mx1, 2));
            const float mN0 = fmaxf(mOld0, mx0);
            const float mN1 = fmaxf(mOld1, mx1);
            const float al0 = __expf(mOld0 - mN0);
            const float al1 = __expf(mOld1 - mN1);
            mOld0 = mN0; mOld1 = mN1;

            uint32_t pk[8][2];
            float sum0 = 0.f, sum1 = 0.f;
#pragma unroll
            for (int nf = 0; nf < 8; nf++) {
                const float p0 = __expf(s[nf][0] - mN0);
                const float p1 = __expf(s[nf][1] - mN0);
                const float p2 = __expf(s[nf][2] - mN1);
                const float p3 = __expf(s[nf][3] - mN1);
                sum0 += p0 + p1; sum1 += p2 + p3;
                pk[nf][0] = pack_h2(p0, p1);
                pk[nf][1] = pack_h2(p2, p3);
            }
            sum0 += __shfl_xor_sync(0xffffffffu, sum0, 1);
            sum0 += __shfl_xor_sync(0xffffffffu, sum0, 2);
            sum1 += __shfl_xor_sync(0xffffffffu, sum1, 1);
            sum1 += __shfl_xor_sync(0xffffffffu, sum1, 2);
            l0 = l0 * al0 + sum0;
            l1 = l1 * al1 + sum1;

#pragma unroll
            for (int nf = 0; nf < 8; nf++) {
                o[nf][0] *= al0; o[nf][1] *= al0;
                o[nf][2] *= al1; o[nf][3] *= al1;
            }

            // ---- O += P V (P fragments from registers; V via ldmatrix.trans) ----
#pragma unroll
            for (int kc = 0; kc < 4; kc++) {
                uint32_t a[4];
                a[0] = pk[2 * kc][0];     a[1] = pk[2 * kc][1];
                a[2] = pk[2 * kc + 1][0]; a[3] = pk[2 * kc + 1][1];
                const int krow = kc * 16 + vkl;
#pragma unroll
                for (int po = 0; po < 4; po++) {
                    const int nchunk = po * 2 + vch;
                    uint32_t bt[4];
                    ldsm_x4_t(bt, vbase + (uint32_t)(krow * 128) +
                              (uint32_t)((nchunk ^ (krow & 7)) << 4));
                    mma_f16(o[po * 2 + 0], a, bt[0], bt[1]);
                    mma_f16(o[po * 2 + 1], a, bt[2], bt[3]);
                }
            }
        }
    }

    // ---- normalize + write y (fp16) ----
    const float il0 = 1.0f / l0;
    const float il1 = 1.0f / l1;
    const int r0 = m0 + lq;
#pragma unroll
    for (int nf = 0; nf < 8; nf++) {
        const int c0 = nf * 8 + 2 * lr4;
        const size_t ob0 = ((size_t)(b * Tn + qi * 128 + r0)) * Cn + h * 64 + c0;
        const size_t ob1 = ((size_t)(b * Tn + qi * 128 + r0 + 8)) * Cn + h * 64 + c0;
        *(__half2*)&Yg[ob0] =
            __float22half2_rn(make_float2(o[nf][0] * il0, o[nf][1] * il0));
        *(__half2*)&Yg[ob1] =
            __float22half2_rn(make_float2(o[nf][2] * il1, o[nf][3] * il1));
    }
#undef KV_ISSUE
}

// ---------------------------------------------------------------------------
extern "C" void kernel_launch(void* const* d_in, const int* in_sizes, int n_in,
                              void* d_out, int out_size)
{
    const float* x  = (const float*)d_in[0];
    const float* Wq = (const float*)d_in[1];
    const float* Wk = (const float*)d_in[2];
    const float* Wv = (const float*)d_in[3];
    const float* Wo = (const float*)d_in[4];
    float* out = (float*)d_out;

    __half *q, *k, *v, *y, *xh, *wh;
    cudaGetSymbolAddress((void**)&q,  g_q);
    cudaGetSymbolAddress((void**)&k,  g_k);
    cudaGetSymbolAddress((void**)&v,  g_v);
    cudaGetSymbolAddress((void**)&y,  g_y);
    cudaGetSymbolAddress((void**)&xh, g_xh);
    cudaGetSymbolAddress((void**)&wh, g_wh);
    __half* wq_h = wh;
    __half* wk_h = wh + (size_t)Cn * Cn;
    __half* wv_h = wh + (size_t)2 * Cn * Cn;
    __half* wo_h = wh + (size_t)3 * Cn * Cn;

    cudaFuncSetAttribute(gemm_h<true>,  cudaFuncAttributeMaxDynamicSharedMemorySize, GEMM_SMEM_BYTES);
    cudaFuncSetAttribute(gemm_h<false>, cudaFuncAttributeMaxDynamicSharedMemorySize, GEMM_SMEM_BYTES);
    cudaFuncSetAttribute(attn_h, cudaFuncAttributeMaxDynamicSharedMemorySize, ATTN_SMEM_BYTES);

    // 0) convert inputs to fp16
    prep_h<<<dim3(8192, 5), 256>>>(x, Wq, Wk, Wv, Wo);
    // 1) QKV projections + fused RoPE (q scaled by 1/8); 64x64 tiles
    gemm_h<true><<<dim3(Cn / 64, Mrows / 64, 3), 128, GEMM_SMEM_BYTES>>>(
        xh, wq_h, wk_h, wv_h, q, k, v, 1);
    // 2) causal flash attention (k-tile 128)
    attn_h<<<dim3(Tn / 128, Hn, Bn), 256, ATTN_SMEM_BYTES>>>(q, k, v, y);
    // 3) output projection (fp16 in, fp32 out); 64x64 tiles
    gemm_h<false><<<dim3(Cn / 64, Mrows / 64, 1), 128, GEMM_SMEM_BYTES>>>(
        y, wo_h, wo_h, wo_h, out, out, out, 0);
}